// round 16
// baseline (speedup 1.0000x reference)
#include <cuda_runtime.h>
#include <cuda_bf16.h>
#include <cstdint>

// Problem constants (fixed by the reference)
#define NN   50000
#define EE   800000
#define TT   8
#define CIN  16
#define HID  16
#define COUT 32
#define ROW  (TT*CIN)   // 128 floats per node row (layer1 input & layer2 input both 128)

// Scratch (device globals — no allocation allowed)
__device__ float g_x0 [NN * ROW];   // X transposed to [N, T*CIN]
__device__ float g_h1 [NN * ROW];   // layer-1 output [N, T*HID]
__device__ float g_agg[NN * ROW];   // aggregation buffer (reused per layer)
__device__ float g_cnt[NN];         // per-dst edge counts (reused per layer)

// ---------------------------------------------------------------------------
// K0: transpose X [T,N,C] -> x0 [N, T*C]
__global__ void k_transpose(const float* __restrict__ X, float* __restrict__ x0) {
    int idx = blockIdx.x * blockDim.x + threadIdx.x;
    if (idx >= NN * ROW) return;
    int c = idx & (CIN - 1);
    int t = (idx >> 4) & (TT - 1);
    int n = idx >> 7;
    x0[idx] = X[((size_t)t * NN + n) * CIN + c];
}

// ---------------------------------------------------------------------------
// K1: warp-per-edge scatter:  agg[dst] += w * x[src]   (128 floats/edge)
__global__ void k_scatter(const int* __restrict__ ei, const float* __restrict__ ew,
                          const float* __restrict__ x,
                          float* __restrict__ agg, float* __restrict__ cnt) {
    int gtid = blockIdx.x * blockDim.x + threadIdx.x;
    int e    = gtid >> 5;
    int lane = gtid & 31;
    if (e >= EE) return;

    int   src = __ldg(&ei[e]);
    int   dst = __ldg(&ei[EE + e]);
    float w   = __ldg(&ew[e]);

    const float4* xr = reinterpret_cast<const float4*>(x + (size_t)src * ROW);
    float4 v = __ldg(&xr[lane]);
    v.x *= w; v.y *= w; v.z *= w; v.w *= w;

    float* a = agg + (size_t)dst * ROW + lane * 4;
    asm volatile("red.global.add.v4.f32 [%0], {%1,%2,%3,%4};"
                 :: "l"(a), "f"(v.x), "f"(v.y), "f"(v.z), "f"(v.w) : "memory");

    if (lane == 0) atomicAdd(&cnt[dst], 1.0f);
}

// ---------------------------------------------------------------------------
// K2: layer-1 node op: h1 = leaky( [x, agg/max(cnt,1)] @ W1 + b1 )
// one thread per (n,t)
__global__ void k_node1(const float* __restrict__ x0, const float* __restrict__ agg,
                        const float* __restrict__ cnt,
                        const float* __restrict__ W1, const float* __restrict__ b1,
                        float* __restrict__ h1) {
    __shared__ float sW[2 * CIN * HID];   // 32x16
    __shared__ float sb[HID];
    for (int i = threadIdx.x; i < 2 * CIN * HID; i += blockDim.x) sW[i] = W1[i];
    if (threadIdx.x < HID) sb[threadIdx.x] = b1[threadIdx.x];
    __syncthreads();

    int idx = blockIdx.x * blockDim.x + threadIdx.x;   // n*T + t
    if (idx >= NN * TT) return;
    int n = idx >> 3;
    int t = idx & (TT - 1);

    float inv = 1.0f / fmaxf(cnt[n], 1.0f);
    const float* xr = x0  + (size_t)n * ROW + t * CIN;
    const float* ar = agg + (size_t)n * ROW + t * CIN;

    float out[HID];
#pragma unroll
    for (int d = 0; d < HID; d++) out[d] = sb[d];
#pragma unroll
    for (int c = 0; c < CIN; c++) {
        float xv = xr[c];
        float av = ar[c] * inv;
#pragma unroll
        for (int d = 0; d < HID; d++)
            out[d] += xv * sW[c * HID + d] + av * sW[(CIN + c) * HID + d];
    }
    float* o = h1 + (size_t)n * ROW + t * HID;
#pragma unroll
    for (int d = 0; d < HID; d++) {
        float v = out[d];
        o[d] = v > 0.0f ? v : 0.01f * v;
    }
}

// ---------------------------------------------------------------------------
// K3: layer-2 node op: out = leaky( [h1, agg/max(cnt,1)] @ W2 + b2 )
// writes output in [T, N, COUT] layout. one thread per (n,t)
__global__ void k_node2(const float* __restrict__ h1, const float* __restrict__ agg,
                        const float* __restrict__ cnt,
                        const float* __restrict__ W2, const float* __restrict__ b2,
                        float* __restrict__ out) {
    __shared__ float sW[2 * HID * COUT];  // 32x32
    __shared__ float sb[COUT];
    for (int i = threadIdx.x; i < 2 * HID * COUT; i += blockDim.x) sW[i] = W2[i];
    if (threadIdx.x < COUT) sb[threadIdx.x] = b2[threadIdx.x];
    __syncthreads();

    int idx = blockIdx.x * blockDim.x + threadIdx.x;   // n*T + t
    if (idx >= NN * TT) return;
    int n = idx >> 3;
    int t = idx & (TT - 1);

    float inv = 1.0f / fmaxf(cnt[n], 1.0f);
    const float* xr = h1  + (size_t)n * ROW + t * HID;
    const float* ar = agg + (size_t)n * ROW + t * HID;

    float acc[COUT];
#pragma unroll
    for (int d = 0; d < COUT; d++) acc[d] = sb[d];
#pragma unroll
    for (int c = 0; c < HID; c++) {
        float xv = xr[c];
        float av = ar[c] * inv;
#pragma unroll
        for (int d = 0; d < COUT; d++)
            acc[d] += xv * sW[c * COUT + d] + av * sW[(HID + c) * COUT + d];
    }
    float* o = out + ((size_t)t * NN + n) * COUT;
#pragma unroll
    for (int d = 0; d < COUT; d++) {
        float v = acc[d];
        o[d] = v > 0.0f ? v : 0.01f * v;
    }
}

// ---------------------------------------------------------------------------
extern "C" void kernel_launch(void* const* d_in, const int* in_sizes, int n_in,
                              void* d_out, int out_size) {
    const float* X   = (const float*)d_in[0];
    const int*   ei0 = (const int*)  d_in[1];
    const float* ew0 = (const float*)d_in[2];
    const int*   ei1 = (const int*)  d_in[3];
    const float* ew1 = (const float*)d_in[4];
    // d_in[5], d_in[6]: res_n_id0/1 == arange(N), identity -> ignored
    const float* W1  = (const float*)d_in[7];
    const float* b1  = (const float*)d_in[8];
    const float* W2  = (const float*)d_in[9];
    const float* b2  = (const float*)d_in[10];
    float* out = (float*)d_out;

    float *p_x0, *p_h1, *p_agg, *p_cnt;
    cudaGetSymbolAddress((void**)&p_x0,  g_x0);
    cudaGetSymbolAddress((void**)&p_h1,  g_h1);
    cudaGetSymbolAddress((void**)&p_agg, g_agg);
    cudaGetSymbolAddress((void**)&p_cnt, g_cnt);

    const int TPB = 256;

    // K0: transpose input
    k_transpose<<<(NN * ROW + TPB - 1) / TPB, TPB>>>(X, p_x0);

    // Layer 1
    cudaMemsetAsync(p_agg, 0, sizeof(float) * (size_t)NN * ROW);
    cudaMemsetAsync(p_cnt, 0, sizeof(float) * NN);
    {
        int warps = EE;
        int blocks = (warps * 32 + TPB - 1) / TPB;
        k_scatter<<<blocks, TPB>>>(ei0, ew0, p_x0, p_agg, p_cnt);
    }
    k_node1<<<(NN * TT + TPB - 1) / TPB, TPB>>>(p_x0, p_agg, p_cnt, W1, b1, p_h1);

    // Layer 2
    cudaMemsetAsync(p_agg, 0, sizeof(float) * (size_t)NN * ROW);
    cudaMemsetAsync(p_cnt, 0, sizeof(float) * NN);
    {
        int warps = EE;
        int blocks = (warps * 32 + TPB - 1) / TPB;
        k_scatter<<<blocks, TPB>>>(ei1, ew1, p_h1, p_agg, p_cnt);
    }
    k_node2<<<(NN * TT + TPB - 1) / TPB, TPB>>>(p_h1, p_agg, p_cnt, W2, b2, out);
}

// round 17
// speedup vs baseline: 1.0018x; 1.0018x over previous
#include <cuda_runtime.h>
#include <cuda_bf16.h>
#include <cstdint>

// Problem constants (fixed by the reference)
#define NN   50000
#define EE   800000
#define TT   8
#define CIN  16
#define HID  16
#define COUT 32
#define ROW  (TT*CIN)   // 128 floats per node row (layer1 input & layer2 input both 128)

// Scratch (device globals — no allocation allowed)
__device__ float g_x0 [NN * ROW];   // X transposed to [N, T*CIN]
__device__ float g_h1 [NN * ROW];   // layer-1 output [N, T*HID]
__device__ float g_agg[NN * ROW];   // aggregation buffer (reused per layer)
__device__ float g_cnt[NN];         // per-dst edge counts (reused per layer)

// ---------------------------------------------------------------------------
// K0: transpose X [T,N,C] -> x0 [N, T*C]
__global__ void k_transpose(const float* __restrict__ X, float* __restrict__ x0) {
    int idx = blockIdx.x * blockDim.x + threadIdx.x;
    if (idx >= NN * ROW) return;
    int c = idx & (CIN - 1);
    int t = (idx >> 4) & (TT - 1);
    int n = idx >> 7;
    x0[idx] = X[((size_t)t * NN + n) * CIN + c];
}

// ---------------------------------------------------------------------------
// K1: warp-per-edge scatter:  agg[dst] += w * x[src]   (128 floats/edge)
__global__ void k_scatter(const int* __restrict__ ei, const float* __restrict__ ew,
                          const float* __restrict__ x,
                          float* __restrict__ agg, float* __restrict__ cnt) {
    int gtid = blockIdx.x * blockDim.x + threadIdx.x;
    int e    = gtid >> 5;
    int lane = gtid & 31;
    if (e >= EE) return;

    int   src = __ldg(&ei[e]);
    int   dst = __ldg(&ei[EE + e]);
    float w   = __ldg(&ew[e]);

    const float4* xr = reinterpret_cast<const float4*>(x + (size_t)src * ROW);
    float4 v = __ldg(&xr[lane]);
    v.x *= w; v.y *= w; v.z *= w; v.w *= w;

    float* a = agg + (size_t)dst * ROW + lane * 4;
    asm volatile("red.global.add.v4.f32 [%0], {%1,%2,%3,%4};"
                 :: "l"(a), "f"(v.x), "f"(v.y), "f"(v.z), "f"(v.w) : "memory");

    if (lane == 0) atomicAdd(&cnt[dst], 1.0f);
}

// ---------------------------------------------------------------------------
// K2: layer-1 node op: h1 = leaky( [x, agg/max(cnt,1)] @ W1 + b1 )
// one thread per (n,t)
__global__ void k_node1(const float* __restrict__ x0, const float* __restrict__ agg,
                        const float* __restrict__ cnt,
                        const float* __restrict__ W1, const float* __restrict__ b1,
                        float* __restrict__ h1) {
    __shared__ float sW[2 * CIN * HID];   // 32x16
    __shared__ float sb[HID];
    for (int i = threadIdx.x; i < 2 * CIN * HID; i += blockDim.x) sW[i] = W1[i];
    if (threadIdx.x < HID) sb[threadIdx.x] = b1[threadIdx.x];
    __syncthreads();

    int idx = blockIdx.x * blockDim.x + threadIdx.x;   // n*T + t
    if (idx >= NN * TT) return;
    int n = idx >> 3;
    int t = idx & (TT - 1);

    float inv = 1.0f / fmaxf(cnt[n], 1.0f);
    const float* xr = x0  + (size_t)n * ROW + t * CIN;
    const float* ar = agg + (size_t)n * ROW + t * CIN;

    float out[HID];
#pragma unroll
    for (int d = 0; d < HID; d++) out[d] = sb[d];
#pragma unroll
    for (int c = 0; c < CIN; c++) {
        float xv = xr[c];
        float av = ar[c] * inv;
#pragma unroll
        for (int d = 0; d < HID; d++)
            out[d] += xv * sW[c * HID + d] + av * sW[(CIN + c) * HID + d];
    }
    float* o = h1 + (size_t)n * ROW + t * HID;
#pragma unroll
    for (int d = 0; d < HID; d++) {
        float v = out[d];
        o[d] = v > 0.0f ? v : 0.01f * v;
    }
}

// ---------------------------------------------------------------------------
// K3: layer-2 node op: out = leaky( [h1, agg/max(cnt,1)] @ W2 + b2 )
// writes output in [T, N, COUT] layout. one thread per (n,t)
__global__ void k_node2(const float* __restrict__ h1, const float* __restrict__ agg,
                        const float* __restrict__ cnt,
                        const float* __restrict__ W2, const float* __restrict__ b2,
                        float* __restrict__ out) {
    __shared__ float sW[2 * HID * COUT];  // 32x32
    __shared__ float sb[COUT];
    for (int i = threadIdx.x; i < 2 * HID * COUT; i += blockDim.x) sW[i] = W2[i];
    if (threadIdx.x < COUT) sb[threadIdx.x] = b2[threadIdx.x];
    __syncthreads();

    int idx = blockIdx.x * blockDim.x + threadIdx.x;   // n*T + t
    if (idx >= NN * TT) return;
    int n = idx >> 3;
    int t = idx & (TT - 1);

    float inv = 1.0f / fmaxf(cnt[n], 1.0f);
    const float* xr = h1  + (size_t)n * ROW + t * HID;
    const float* ar = agg + (size_t)n * ROW + t * HID;

    float acc[COUT];
#pragma unroll
    for (int d = 0; d < COUT; d++) acc[d] = sb[d];
#pragma unroll
    for (int c = 0; c < HID; c++) {
        float xv = xr[c];
        float av = ar[c] * inv;
#pragma unroll
        for (int d = 0; d < COUT; d++)
            acc[d] += xv * sW[c * COUT + d] + av * sW[(HID + c) * COUT + d];
    }
    float* o = out + ((size_t)t * NN + n) * COUT;
#pragma unroll
    for (int d = 0; d < COUT; d++) {
        float v = acc[d];
        o[d] = v > 0.0f ? v : 0.01f * v;
    }
}

// ---------------------------------------------------------------------------
extern "C" void kernel_launch(void* const* d_in, const int* in_sizes, int n_in,
                              void* d_out, int out_size) {
    const float* X   = (const float*)d_in[0];
    const int*   ei0 = (const int*)  d_in[1];
    const float* ew0 = (const float*)d_in[2];
    const int*   ei1 = (const int*)  d_in[3];
    const float* ew1 = (const float*)d_in[4];
    // d_in[5], d_in[6]: res_n_id0/1 == arange(N), identity -> ignored
    const float* W1  = (const float*)d_in[7];
    const float* b1  = (const float*)d_in[8];
    const float* W2  = (const float*)d_in[9];
    const float* b2  = (const float*)d_in[10];
    float* out = (float*)d_out;

    float *p_x0, *p_h1, *p_agg, *p_cnt;
    cudaGetSymbolAddress((void**)&p_x0,  g_x0);
    cudaGetSymbolAddress((void**)&p_h1,  g_h1);
    cudaGetSymbolAddress((void**)&p_agg, g_agg);
    cudaGetSymbolAddress((void**)&p_cnt, g_cnt);

    const int TPB = 256;

    // K0: transpose input
    k_transpose<<<(NN * ROW + TPB - 1) / TPB, TPB>>>(X, p_x0);

    // Layer 1
    cudaMemsetAsync(p_agg, 0, sizeof(float) * (size_t)NN * ROW);
    cudaMemsetAsync(p_cnt, 0, sizeof(float) * NN);
    {
        int warps = EE;
        int blocks = (warps * 32 + TPB - 1) / TPB;
        k_scatter<<<blocks, TPB>>>(ei0, ew0, p_x0, p_agg, p_cnt);
    }
    k_node1<<<(NN * TT + TPB - 1) / TPB, TPB>>>(p_x0, p_agg, p_cnt, W1, b1, p_h1);

    // Layer 2
    cudaMemsetAsync(p_agg, 0, sizeof(float) * (size_t)NN * ROW);
    cudaMemsetAsync(p_cnt, 0, sizeof(float) * NN);
    {
        int warps = EE;
        int blocks = (warps * 32 + TPB - 1) / TPB;
        k_scatter<<<blocks, TPB>>>(ei1, ew1, p_h1, p_agg, p_cnt);
    }
    k_node2<<<(NN * TT + TPB - 1) / TPB, TPB>>>(p_h1, p_agg, p_cnt, W2, b2, out);
}